// round 8
// baseline (speedup 1.0000x reference)
#include <cuda_runtime.h>

// ContinuousPositionBias for GB300 — round 8 (MLP: 8t/thread, d-split x2; scatter frozen + partial-sum staging).
// Inputs: 0 glob_pos(1,32,4) f32 | 1 coords_table(2209,2) f32 | 2 rpi(unused)
//         3 W1(2,512) | 4 b1(512) | 5 W2(512,16) | 6 num_prefix_tokens(=1)
// Output: (32,16,577,577) f32

#define NT     2209
#define HEADS  16
#define DHID   512
#define DHALF  256
#define BATCH  32
#define OW     577
#define PLANE  (OW*OW)        // 332929
#define TOTT   (BATCH * NT)   // 70688
#define TT     8              // t per thread

__device__ float g_bias0[BATCH * HEADS * NT];   // partial sum, d in [0,256)
__device__ float g_bias1[BATCH * HEADS * NT];   // partial sum, d in [256,512)

typedef unsigned long long u64;

__device__ __forceinline__ u64 fma2(u64 a, u64 b, u64 c) {
    u64 d;
    asm("fma.rn.f32x2 %0, %1, %2, %3;" : "=l"(d) : "l"(a), "l"(b), "l"(c));
    return d;
}
__device__ __forceinline__ u64 pack2(float x) {
    u64 d;
    asm("mov.b64 %0, {%1, %1};" : "=l"(d) : "f"(x));
    return d;
}
__device__ __forceinline__ void unpack2(u64 v, float& lo, float& hi) {
    asm("mov.b64 {%0, %1}, %2;" : "=f"(lo), "=f"(hi) : "l"(v));
}

// ---------------------------------------------------------------------------
// Kernel A: partial bias over a 256-wide d-range.
// blockIdx.x = 2*tb + dh : tb = t-tile (1024 t), dh = d-half.
// ---------------------------------------------------------------------------
__global__ __launch_bounds__(128) void mlp_kernel(
    const float* __restrict__ glob, const float* __restrict__ ctab,
    const float* __restrict__ W1,   const float* __restrict__ b1,
    const float* __restrict__ W2)
{
    __shared__ __align__(16) float4 w1s[DHALF];          // (W1[0][d], W1[1][d], b1[d], 0)
    __shared__ __align__(16) float  w2s[DHALF * HEADS];  // W2 rows for this d-half

    const int tid = threadIdx.x;
    const int bx  = blockIdx.x;
    const int dh  = bx & 1;
    const int tb  = bx >> 1;
    const int d0  = dh * DHALF;

    {
        const float4* src = (const float4*)(W2 + d0 * HEADS);
        float4* dst = (float4*)w2s;
        #pragma unroll
        for (int k = tid; k < DHALF * HEADS / 4; k += 128) dst[k] = src[k];
        for (int d = tid; d < DHALF; d += 128)
            w1s[d] = make_float4(W1[d0 + d], W1[DHID + d0 + d], b1[d0 + d], 0.0f);
    }
    __syncthreads();

    int  bj[TT], tj[TT];
    bool vj[TT];
    float c0j[TT], c1j[TT];

    #pragma unroll
    for (int j = 0; j < TT; j++) {
        const int flat = tb * (128 * TT) + j * 128 + tid;
        vj[j] = (flat < TOTT);
        const int f = vj[j] ? flat : 0;
        const int b = f / NT;
        const int t = f - b * NT;
        const float g0 = glob[b*4+0], g1 = glob[b*4+1];
        const float g2 = glob[b*4+2], g3 = glob[b*4+3];
        float p0 = g2 / g0 * 8.0f;
        float p1 = g3 / g1 * 8.0f;
        p0 = copysignf(log2f(fabsf(p0) + 1.0f), p0) * (2.0f / 3.0f) - 1.0f;
        p1 = copysignf(log2f(fabsf(p1) + 1.0f), p1) * (2.0f / 3.0f) - 1.0f;
        bj[j]  = b; tj[j] = t;
        c0j[j] = ctab[2*t]   + p0;
        c1j[j] = ctab[2*t+1] + p1;
    }

    u64 acc[TT][8];
    #pragma unroll
    for (int j = 0; j < TT; j++)
        #pragma unroll
        for (int k = 0; k < 8; k++) acc[j][k] = 0ull;

    const ulonglong2* __restrict__ w2q = (const ulonglong2*)w2s;

    #pragma unroll 2
    for (int d = 0; d < DHALF; d++) {
        const float4 w = w1s[d];
        const ulonglong2 q0 = w2q[d*4 + 0];
        const ulonglong2 q1 = w2q[d*4 + 1];
        const ulonglong2 q2 = w2q[d*4 + 2];
        const ulonglong2 q3 = w2q[d*4 + 3];
        #pragma unroll
        for (int j = 0; j < TT; j++) {
            const float hd = fmaxf(fmaf(c0j[j], w.x, fmaf(c1j[j], w.y, w.z)), 0.0f);
            const u64 hd2 = pack2(hd);
            acc[j][0] = fma2(hd2, q0.x, acc[j][0]);
            acc[j][1] = fma2(hd2, q0.y, acc[j][1]);
            acc[j][2] = fma2(hd2, q1.x, acc[j][2]);
            acc[j][3] = fma2(hd2, q1.y, acc[j][3]);
            acc[j][4] = fma2(hd2, q2.x, acc[j][4]);
            acc[j][5] = fma2(hd2, q2.y, acc[j][5]);
            acc[j][6] = fma2(hd2, q3.x, acc[j][6]);
            acc[j][7] = fma2(hd2, q3.y, acc[j][7]);
        }
    }

    float* __restrict__ gb = dh ? g_bias1 : g_bias0;
    #pragma unroll
    for (int j = 0; j < TT; j++) {
        if (!vj[j]) continue;
        float* outb = gb + (size_t)bj[j] * (HEADS * NT) + tj[j];
        #pragma unroll
        for (int k = 0; k < 8; k++) {
            float lo, hi; unpack2(acc[j][k], lo, hi);
            outb[(2*k)   * NT] = lo;
            outb[(2*k+1) * NT] = hi;
        }
    }
}

// ---------------------------------------------------------------------------
// Kernel B — diagonal-window scatter (round-5 frozen); staging sums the two
// d-half partials.
//   val(r=1+24ib+ii, c>=1) = rev[(23-ii) + f(c)],  f(c)=(c-1)+23*((c-1)/24)
// ---------------------------------------------------------------------------
#define FRONT 32

__global__ __launch_bounds__(192) void scatter_kernel(float* __restrict__ out)
{
    __shared__ float sh[1536];
    const int tid   = threadIdx.x;
    const int ib    = blockIdx.x;     // 0..23 bands, 24 = zero-row writer
    const int plane = blockIdx.y;     // 0..511
    float* __restrict__ pb = out + (size_t)plane * PLANE;

    if (ib == 24) {                   // row 0 is all zeros
        for (int c = tid; c < OW; c += 192) pb[c] = 0.0f;
        return;
    }

    const float* __restrict__ bp0 = g_bias0 + (size_t)plane * NT + 47 * ib;
    const float* __restrict__ bp1 = g_bias1 + (size_t)plane * NT + 47 * ib;
    for (int u = tid; u < 1128; u += 192) {
        int a = (1127 - u) + FRONT;
        sh[a + (a >> 2)] = bp0[u] + bp1[u];
    }
    __syncthreads();

    const int w     = tid >> 5;
    const int lane  = tid & 31;
    const int ii0   = 4 * w;
    const int r0    = 1 + 24 * ib + ii0;
    const int basev = 23 - ii0;
    const int alpha = (int)(((size_t)plane * PLANE + (size_t)r0 * OW) & 3);
    const int cs    = (4 - alpha) & 3;
    float* __restrict__ rp = pb + (size_t)r0 * OW;

    for (int t = 0; t < 5; t++) {
        const int k = lane + 32 * t;
        if (k > 144) continue;
        const int cbase = cs + 4 * k;

        if (cbase >= 4 && cbase <= 573) {
            const int j0 = cbase - 1;
            const int q0 = (j0 * 2731) >> 16;
            const int m0 = j0 - 24 * q0;
            const int A  = basev + j0 + 23 * q0 + FRONT;

            float wv[10], wc5[5];
            {
                const int aW = A - 6;
                #pragma unroll
                for (int i = 0; i < 10; i++) { int a = aW + i; wv[i] = sh[a + (a >> 2)]; }
                const int aC = (m0 <= 2) ? (A - 29) : (A + 22);
                #pragma unroll
                for (int i = 0; i < 5; i++) { int a = aC + i; wc5[i] = sh[a + (a >> 2)]; }
            }

            #pragma unroll
            for (int di = 0; di < 4; di++) {
                float4 v;
                float* vv = (float*)&v;
                #pragma unroll
                for (int e = 0; e < 4; e++) {
                    const int x   = e - di;
                    const int idx = e - 2 * di + 6;
                    if (x > 0) {
                        vv[e] = (m0 >= 24 - x) ? wc5[idx - 5] : wv[idx];
                    } else if (x < 0) {
                        vv[e] = (m0 <  -x)     ? wc5[idx]     : wv[idx];
                    } else {
                        vv[e] = wv[idx];
                    }
                }
                *(float4*)(rp + di * OW + (cbase - di)) = v;
            }
        } else {
            #pragma unroll
            for (int di = 0; di < 4; di++) {
                int clo = (k == 0) ? 0 : (cbase - di);
                int chi = cbase - di + 3;
                if (chi > 576) chi = 576;
                for (int c = clo; c <= chi; c++) {
                    float val = 0.0f;
                    if (c >= 1) {
                        const int j = c - 1;
                        const int q = (j * 2731) >> 16;
                        const int a = basev - di + j + 23 * q + FRONT;
                        val = sh[a + (a >> 2)];
                    }
                    rp[di * OW + c] = val;
                }
            }
        }
    }
}

// ---------------------------------------------------------------------------
extern "C" void kernel_launch(void* const* d_in, const int* in_sizes, int n_in,
                              void* d_out, int out_size)
{
    const float* glob = (const float*)d_in[0];
    const float* ctab = (const float*)d_in[1];
    const float* W1   = (const float*)d_in[3];
    const float* b1   = (const float*)d_in[4];
    const float* W2   = (const float*)d_in[5];
    float* out        = (float*)d_out;

    const int tblocks = (TOTT + 128 * TT - 1) / (128 * TT);   // 70
    mlp_kernel<<<dim3(2 * tblocks), 128>>>(glob, ctab, W1, b1, W2);
    scatter_kernel<<<dim3(25, BATCH * HEADS), 192>>>(out);
}